// round 1
// baseline (speedup 1.0000x reference)
#include <cuda_runtime.h>

// Problem constants
#define Bb 2
#define Hh 8
#define NCC 32
#define CC 64
#define OO 2
#define DD 128
#define BH (Bb*Hh)              // 16
#define NTILES (BH*NCC)         // 512
#define TILE_STRIDE (CC*OO*DD)  // 16384
#define OUT_ELEMS (NTILES*TILE_STRIDE) // 8388608

// Per-chunk recurrent states h0 used by each tile: states[bh*NC+n][128][128]
__device__ float g_states[NTILES * DD * DD];   // 33.5 MB static scratch

// ---------------------------------------------------------------------------
// Chain kernel: 16 blocks (one per (b,h)), sequential over 32 chunks.
// Only position c=63 matters for the state recurrence. With O=2:
//   uv0 = u0 - w0^T H
//   uv1 = u1 - a0 .* (w1^T H) - (w1.w0) * uv0
//   H'  = H .* (a0.*a1)[e] + w0[d]*(uv0.*a1)[e] + w1[d]*uv1[e]
// then rowwise-norm gelu activation (unless linear_activation).
// ---------------------------------------------------------------------------
__global__ __launch_bounds__(256) void chain_kernel(
    const float* __restrict__ q, const float* __restrict__ w,
    const float* __restrict__ u, const float* __restrict__ a,
    const float* __restrict__ init, const int* __restrict__ linflag,
    float* __restrict__ dout)
{
    extern __shared__ float sm[];
    float* Hs    = sm;                 // 128 * 129 (padded pitch)
    float* vw0   = Hs + 128*129;       // 128
    float* vw1   = vw0 + 128;
    float* vu0   = vw1 + 128;
    float* vu1   = vu0 + 128;
    float* va0   = vu1 + 128;
    float* va1   = va0 + 128;
    float* kth   = va1 + 128;          // 2*128
    float* coefA = kth + 256;          // 128
    float* coefB = coefA + 128;        // 128
    float* coefC = coefB + 128;        // 128
    float* norms = coefC + 128;        // 128
    float* ssww  = norms + 128;        // 1

    const int t  = threadIdx.x;
    const int bh = blockIdx.x;
    const int lin = *linflag;

    // Load initial state
    const float* ip = init + bh * (DD*DD);
    for (int k = t; k < DD*DD; k += 256)
        Hs[(k >> 7) * 129 + (k & 127)] = ip[k];
    __syncthreads();

    for (int n = 0; n < NCC; n++) {
        // Publish h0 for this chunk's output tile
        float* sp = g_states + (bh * NCC + n) * (DD*DD);
        for (int k = t; k < DD*DD; k += 256)
            sp[k] = Hs[(k >> 7) * 129 + (k & 127)];

        // Load the c=63 vectors for both orders
        int base = ((bh * NCC + n) * CC + (CC - 1)) * (OO * DD);
        if (t < 128) {
            vw0[t] = w[base + t];        vw1[t] = w[base + DD + t];
            vu0[t] = u[base + t];        vu1[t] = u[base + DD + t];
            va0[t] = a[base + t];        va1[t] = a[base + DD + t];
        }
        __syncthreads();

        // scalar w1 . w0 (warp 0)
        if (t < 32) {
            float s = 0.f;
            #pragma unroll
            for (int i = 0; i < 4; i++) s += vw0[t + 32*i] * vw1[t + 32*i];
            #pragma unroll
            for (int o = 16; o; o >>= 1) s += __shfl_xor_sync(0xffffffffu, s, o);
            if (t == 0) *ssww = s;
        }
        __syncthreads();

        // kth0[e] = w0^T H, kth1[e] = w1^T H
        {
            const int e = t & 127, g = t >> 7;
            const float* wv = g ? vw1 : vw0;
            float acc = 0.f;
            #pragma unroll 8
            for (int d = 0; d < DD; d++)
                acc = fmaf(wv[d], Hs[d*129 + e], acc);
            kth[g*128 + e] = acc;
        }
        __syncthreads();

        if (t < 128) {
            float sww = *ssww;
            float uv0 = vu0[t] - kth[t];
            float uv1 = vu1[t] - va0[t]*kth[128 + t] - sww*uv0;
            coefA[t] = va0[t] * va1[t];
            coefB[t] = uv0 * va1[t];
            coefC[t] = uv1;
        }
        __syncthreads();

        // State update (fused over both orders)
        {
            const int e = t & 127, g = t >> 7;
            const float cA = coefA[e], cB = coefB[e], cC = coefC[e];
            #pragma unroll 4
            for (int d = g*64; d < g*64 + 64; d++) {
                float h = Hs[d*129 + e];
                Hs[d*129 + e] = fmaf(h, cA, fmaf(vw0[d], cB, vw1[d]*cC));
            }
        }
        __syncthreads();

        if (!lin) {
            // Row norms over e
            if (t < 128) {
                float s = 0.f;
                #pragma unroll 8
                for (int e = 0; e < 128; e++) { float v = Hs[t*129 + e]; s = fmaf(v, v, s); }
                norms[t] = sqrtf(s) + 1e-6f;
            }
            __syncthreads();
            // h = x/2 * gelu_tanh(2x/n) = 0.25*x*z*(1+tanh(0.79788456*(z+0.044715 z^3)))
            {
                const int e = t & 127, g = t >> 7;
                for (int d = g*64; d < g*64 + 64; d++) {
                    float x = Hs[d*129 + e];
                    float z = 2.f * x / norms[d];
                    float inner = 0.7978845608028654f * fmaf(0.044715f*z*z, z, z);
                    float th = tanhf(inner);
                    Hs[d*129 + e] = 0.25f * x * z * (1.f + th);
                }
            }
            __syncthreads();
        }
    }

    // h_final goes after the main output block
    float* hf = dout + OUT_ELEMS + bh * (DD*DD);
    for (int k = t; k < DD*DD; k += 256)
        hf[k] = Hs[(k >> 7) * 129 + (k & 127)];
}

// ---------------------------------------------------------------------------
// Output kernel: one block per (b,h,n) tile (512 blocks).
// Computes M = X * H where X rows = {q0,w0,q1,w1} x 64 positions (256x128),
// H = h0 (128x128). Then elementwise epilogue produces out0/out1.
// ---------------------------------------------------------------------------
#define XPITCH 257
__global__ __launch_bounds__(256, 1) void out_kernel(
    const float* __restrict__ q, const float* __restrict__ w,
    const float* __restrict__ u, const float* __restrict__ a,
    float* __restrict__ out)
{
    extern __shared__ float sm[];
    float* XsT   = sm;                       // 128 * 257 (K-major transposed X)
    float* Hs    = XsT + 128*XPITCH;         // 128 * 128
    float* partw = Hs + 128*128;             // 256
    float* partq = partw + 256;              // 256
    float* sww   = partq + 256;              // 64
    float* sqw   = sww + 64;                 // 64

    const int t = threadIdx.x;
    const int tile = blockIdx.x;
    const int base = tile * TILE_STRIDE;

    // Load H (h0 for this chunk)
    const float* hp = g_states + tile * (DD*DD);
    for (int k = t; k < DD*DD; k += 256) Hs[k] = hp[k];

    // Load X transposed: row r = type*64 + c, types {0:q0, 1:w0, 2:q1, 3:w1}
    #pragma unroll
    for (int v = 0; v < 4; v++) {
        const float* src = (v & 1) ? w : q;
        const int s = v >> 1;
        for (int k = t; k < CC*DD; k += 256) {
            int c = k >> 7, d = k & 127;
            XsT[d*XPITCH + v*64 + c] = src[base + c*(OO*DD) + s*DD + d];
        }
    }
    __syncthreads();

    // Per-position scalars w1.w0 and q1.w0
    {
        const int c = t >> 2, p = t & 3;
        float pw = 0.f, pq = 0.f;
        #pragma unroll 8
        for (int i = 0; i < 32; i++) {
            int d = p*32 + i;
            float w0v = XsT[d*XPITCH + 64 + c];
            pw = fmaf(XsT[d*XPITCH + 192 + c], w0v, pw);
            pq = fmaf(XsT[d*XPITCH + 128 + c], w0v, pq);
        }
        partw[t] = pw; partq[t] = pq;
    }
    __syncthreads();
    if (t < 64) {
        sww[t] = partw[t*4] + partw[t*4+1] + partw[t*4+2] + partw[t*4+3];
        sqw[t] = partq[t*4] + partq[t*4+1] + partq[t*4+2] + partq[t*4+3];
    }
    __syncthreads();

    // Register-blocked GEMM: thread (tr, tc) computes rows {tr+32i}, cols {16tc+j}
    const int tr = t & 31, tc = t >> 5;
    float acc[8][16];
    #pragma unroll
    for (int i = 0; i < 8; i++)
        #pragma unroll
        for (int j = 0; j < 16; j++) acc[i][j] = 0.f;

    #pragma unroll 2
    for (int d = 0; d < DD; d++) {
        float av[8];
        #pragma unroll
        for (int i = 0; i < 8; i++) av[i] = XsT[d*XPITCH + tr + 32*i];
        float bv[16];
        #pragma unroll
        for (int jb = 0; jb < 4; jb++) {
            float4 bb = *(const float4*)&Hs[d*DD + tc*16 + jb*4];
            bv[jb*4+0] = bb.x; bv[jb*4+1] = bb.y; bv[jb*4+2] = bb.z; bv[jb*4+3] = bb.w;
        }
        #pragma unroll
        for (int i = 0; i < 8; i++)
            #pragma unroll
            for (int j = 0; j < 16; j++)
                acc[i][j] = fmaf(av[i], bv[j], acc[i][j]);
    }

    // Epilogue: row r = tr+32i  ->  type = i>>1, cpair = i&1, c = tr + 32*(i&1)
    // i = type*2 + cp: Aq0=acc[cp], Aw0=acc[2+cp], Aq1=acc[4+cp], Aw1=acc[6+cp]
    const int e0 = tc * 16;
    #pragma unroll
    for (int cp = 0; cp < 2; cp++) {
        const int c = tr + 32*cp;
        const int cb = base + c*(OO*DD);
        const float cw = sww[c], cq = sqw[c];
        #pragma unroll
        for (int jb = 0; jb < 4; jb++) {
            float4 t4;
            t4 = *(const float4*)&q[cb + e0 + jb*4];       float q0v[4] = {t4.x,t4.y,t4.z,t4.w};
            t4 = *(const float4*)&u[cb + e0 + jb*4];       float u0v[4] = {t4.x,t4.y,t4.z,t4.w};
            t4 = *(const float4*)&a[cb + e0 + jb*4];       float a0v[4] = {t4.x,t4.y,t4.z,t4.w};
            t4 = *(const float4*)&q[cb + DD + e0 + jb*4];  float q1v[4] = {t4.x,t4.y,t4.z,t4.w};
            t4 = *(const float4*)&u[cb + DD + e0 + jb*4];  float u1v[4] = {t4.x,t4.y,t4.z,t4.w};
            float o0[4], o1[4];
            #pragma unroll
            for (int jj = 0; jj < 4; jj++) {
                const int j = jb*4 + jj;
                float uv0  = u0v[jj] - acc[2+cp][j];
                float out0 = fmaf(q0v[jj], uv0, acc[0+cp][j]);
                float kth1 = fmaf(cw, uv0, a0v[jj]*acc[6+cp][j]);
                float uv1  = u1v[jj] - kth1;
                float oi1  = fmaf(cq, uv0, a0v[jj]*acc[4+cp][j]);
                float out1 = fmaf(q1v[jj], uv1, oi1);
                o0[jj] = out0; o1[jj] = out1;
            }
            *(float4*)&out[cb + e0 + jb*4]      = make_float4(o0[0],o0[1],o0[2],o0[3]);
            *(float4*)&out[cb + DD + e0 + jb*4] = make_float4(o1[0],o1[1],o1[2],o1[3]);
        }
    }
}

// ---------------------------------------------------------------------------

#define CHAIN_SMEM_BYTES ((128*129 + 6*128 + 256 + 3*128 + 128 + 8) * 4)
#define OUT_SMEM_BYTES   ((128*XPITCH + 128*128 + 256 + 256 + 64 + 64) * 4)

extern "C" void kernel_launch(void* const* d_in, const int* in_sizes, int n_in,
                              void* d_out, int out_size) {
    const float* q    = (const float*)d_in[0];
    const float* w    = (const float*)d_in[1];
    const float* u    = (const float*)d_in[2];
    const float* a    = (const float*)d_in[3];
    const float* init = (const float*)d_in[4];
    const int*   lin  = (const int*)d_in[5];
    float* out = (float*)d_out;

    cudaFuncSetAttribute(chain_kernel, cudaFuncAttributeMaxDynamicSharedMemorySize, CHAIN_SMEM_BYTES);
    cudaFuncSetAttribute(out_kernel,   cudaFuncAttributeMaxDynamicSharedMemorySize, OUT_SMEM_BYTES);

    chain_kernel<<<BH, 256, CHAIN_SMEM_BYTES>>>(q, w, u, a, init, lin, out);
    out_kernel<<<NTILES, 256, OUT_SMEM_BYTES>>>(q, w, u, a, out);
}